// round 16
// baseline (speedup 1.0000x reference)
#include <cuda_runtime.h>
#include <cuda_fp16.h>
#include <cstdint>
#include <math.h>

#define Bb 2
#define Tt 2048
#define TCc 512
#define Cc 1024
#define CCc 512
#define Hh 16
#define Dd 64

#define NX (Bb*Tt*Cc)      // 4194304
#define NC (Bb*TCc*CCc)    // 524288

// ---------------------------------------------------------------------------
// Scratch (__device__ globals; no allocation allowed)
// ---------------------------------------------------------------------------
__device__ __half g_xh[NX];
__device__ __half g_ch[NC];
__device__ __half g_yh[Bb*Tt*Cc];

// fused projection outputs: [B*T, 4096] = [q | k | v | qc], single fp16
// q and qc columns are PRE-SCALED by cs = 0.125 * log2(e).
__device__ __half g_qkvh[Bb*Tt*4*Cc];
// fused cross outputs: [B*TC, 2048] = [kc | vc], single fp16
__device__ __half g_kvch[Bb*TCc*2*Cc];

// fused transposed weights (single fp16)
__device__ __half g_W4_h[4*Cc*Cc];
__device__ __half g_W2_h[2*Cc*CCc];
__device__ __half g_Wp_h[Cc*Cc];
__device__ float g_b4[4*Cc], g_b2[2*Cc];

// persistent work counters + row-block readiness
__device__ int g_actr;          // attention work items
__device__ int g_octr;          // out-proj tiles
__device__ int g_rowcnt[32];    // heads completed per 128-row block of y

#define CSF 0.18033688011f   // 0.125 * log2(e)

// ---------------------------------------------------------------------------
// helpers
// ---------------------------------------------------------------------------
__device__ __forceinline__ uint32_t smem_u32(const void* p) {
    uint32_t a;
    asm("{ .reg .u64 t; cvta.to.shared.u64 t, %1; cvt.u32.u64 %0, t; }"
        : "=r"(a) : "l"(p));
    return a;
}
__device__ __forceinline__ float ex2(float x) {
    float y; asm("ex2.approx.ftz.f32 %0, %1;" : "=f"(y) : "f"(x)); return y;
}

#define CP_ASYNC16(dst, src) \
    asm volatile("cp.async.cg.shared.global [%0], [%1], 16;" :: "r"(dst), "l"(src))
#define CP_COMMIT() asm volatile("cp.async.commit_group;" ::: "memory")
#define CP_WAIT0()  asm volatile("cp.async.wait_group 0;" ::: "memory")
#define CP_WAIT1()  asm volatile("cp.async.wait_group 1;" ::: "memory")

#define LDSM_X4(r0, r1, r2, r3, a) \
    asm volatile("ldmatrix.sync.aligned.m8n8.x4.shared.b16 {%0,%1,%2,%3}, [%4];" \
                 : "=r"(r0), "=r"(r1), "=r"(r2), "=r"(r3) : "r"(a))
#define LDSM_X4T(r0, r1, r2, r3, a) \
    asm volatile("ldmatrix.sync.aligned.m8n8.x4.trans.shared.b16 {%0,%1,%2,%3}, [%4];" \
                 : "=r"(r0), "=r"(r1), "=r"(r2), "=r"(r3) : "r"(a))

#define MMA_F16(d, a, b) \
    asm volatile("mma.sync.aligned.m16n8k16.row.col.f32.f16.f16.f32 " \
                 "{%0,%1,%2,%3}, {%4,%5,%6,%7}, {%8,%9}, {%0,%1,%2,%3};" \
                 : "+f"((d)[0]), "+f"((d)[1]), "+f"((d)[2]), "+f"((d)[3]) \
                 : "r"((a)[0]), "r"((a)[1]), "r"((a)[2]), "r"((a)[3]), \
                   "r"((b)[0]), "r"((b)[1]))

// ---------------------------------------------------------------------------
// merged prep kernel:
//   blocks [0, 6144): weight transposes (256 threads as 32x8)
//   blocks [6144, ..): cvt x, cvt cross, bias concat, counter resets
// ---------------------------------------------------------------------------
#define TRB 6144
#define MISC_N (NX + NC + 6144 + 40)

__global__ void prep_kernel(
    const float* __restrict__ x, const float* __restrict__ cross,
    const float* __restrict__ Wq,  const float* __restrict__ Wk,
    const float* __restrict__ Wv,  const float* __restrict__ Wcq,
    const float* __restrict__ Wck, const float* __restrict__ Wcv,
    const float* __restrict__ Wp,
    const float* __restrict__ bq, const float* __restrict__ bk,
    const float* __restrict__ bv, const float* __restrict__ bcq,
    const float* __restrict__ bck, const float* __restrict__ bcv)
{
    const int tblk = blockIdx.x;
    if (tblk < TRB) {
        // ---- weight transpose ----
        int z, base;
        if (tblk < 4096)      { z = tblk >> 10;              base = tblk & 1023; }
        else if (tblk < 5120) { z = 4 + ((tblk - 4096) >> 9); base = (tblk - 4096) & 511; }
        else                  { z = 6;                        base = tblk - 5120; }
        const float* W;
        __half* Th;
        int K;
        switch (z) {
            case 0: W = Wq;  Th = g_W4_h;               K = 1024; break;
            case 1: W = Wk;  Th = g_W4_h + 1024 * 1024; K = 1024; break;
            case 2: W = Wv;  Th = g_W4_h + 2048 * 1024; K = 1024; break;
            case 3: W = Wcq; Th = g_W4_h + 3072 * 1024; K = 1024; break;
            case 4: W = Wck; Th = g_W2_h;               K = 512;  break;
            case 5: W = Wcv; Th = g_W2_h + 1024 * 512;  K = 512;  break;
            default: W = Wp; Th = g_Wp_h;               K = 1024; break;
        }
        const int n0 = (base & 31) * 32, k0 = (base >> 5) * 32;
        const int tx = threadIdx.x & 31, ty = threadIdx.x >> 5;

        __shared__ float t[32][33];
        #pragma unroll
        for (int i = 0; i < 4; i++)
            t[ty + 8 * i][tx] = W[(size_t)(k0 + ty + 8 * i) * 1024 + n0 + tx];
        __syncthreads();
        #pragma unroll
        for (int i = 0; i < 4; i++) {
            float v = t[tx][ty + 8 * i];
            Th[(size_t)(n0 + ty + 8 * i) * K + k0 + tx] = __float2half(v);
        }
        return;
    }

    // ---- misc: cvt + bias concat + counters ----
    const int i = (tblk - TRB) * 256 + threadIdx.x;
    if (i < NX) {
        g_xh[i] = __float2half(x[i]);
    } else if (i < NX + NC) {
        g_ch[i - NX] = __float2half(cross[i - NX]);
    } else if (i < NX + NC + 6144) {
        int j = i - NX - NC;
        if (j < 4096) {
            const float* s[4] = {bq, bk, bv, bcq};
            g_b4[j] = s[j >> 10][j & 1023];
        } else {
            int k = j - 4096;
            g_b2[k] = (k < 1024) ? bck[k] : bcv[k - 1024];
        }
    } else if (i < MISC_N) {
        int j = i - (NX + NC + 6144);
        if (j == 0) g_actr = 0;
        else if (j == 1) g_octr = 0;
        else if (j < 34) g_rowcnt[j - 2] = 0;
    }
}

// ---------------------------------------------------------------------------
// single-term HMMA GEMM body
// ---------------------------------------------------------------------------
#define BKg 32
#define LDAg 40
#define TILEB (128 * LDAg * 2)
#define STG1 (2 * TILEB)
#define SM1 (3 * STG1)          // 61440

__device__ __forceinline__ void gemm_body(
    const __half* Ah, const __half* Bh, const float* bias,
    float* outf, __half* outh,
    int N, int K, int bm, int bn, int qscale, char* smem)
{
    const uint32_t sb = smem_u32(smem);
    const int tid = threadIdx.x;
    const int wid = tid >> 5, lane = tid & 31;
    const int wr = wid & 3;
    const int wc = wid >> 2;

    const char* gA = (const char*)(Ah + (size_t)bm * K);
    const char* gB = (const char*)(Bh + (size_t)bn * K);

    const int row0 = tid >> 2, c16a = tid & 3;
    const int row1 = (tid + 256) >> 2;

    auto load_tile = [&](const char* g, uint32_t d, int kb) {
        g += (size_t)kb * (BKg * 2);
        CP_ASYNC16(d + row0 * (LDAg * 2) + c16a * 16,
                   g + (size_t)row0 * (K * 2) + c16a * 16);
        CP_ASYNC16(d + row1 * (LDAg * 2) + c16a * 16,
                   g + (size_t)row1 * (K * 2) + c16a * 16);
    };
    auto load_chunk = [&](int kb, int st) {
        const uint32_t sdst = sb + st * STG1;
        load_tile(gA, sdst, kb);
        load_tile(gB, sdst + TILEB, kb);
    };

    float acc[2][8][4] = {};

    const int nchunks = K / BKg;
    load_chunk(0, 0); CP_COMMIT();
    load_chunk(1, 1); CP_COMMIT();

    for (int kb = 0; kb < nchunks; kb++) {
        const int st = kb % 3;
        if (kb + 1 < nchunks) { CP_WAIT1(); } else { CP_WAIT0(); }
        __syncthreads();
        if (kb + 2 < nchunks) { load_chunk(kb + 2, (kb + 2) % 3); CP_COMMIT(); }

        const uint32_t ah = sb + st * STG1;
        const uint32_t bh = ah + TILEB;

        #pragma unroll
        for (int ks = 0; ks < 2; ks++) {
            const int k0 = ks * 16;
            uint32_t Ahf[2][4], Bhf[8][2];

            #pragma unroll
            for (int mt = 0; mt < 2; mt++) {
                const int arow = wr * 32 + mt * 16 + (lane & 15);
                const int acol = k0 + (lane >> 4) * 8;
                const uint32_t ao = (uint32_t)(arow * LDAg + acol) * 2;
                LDSM_X4(Ahf[mt][0], Ahf[mt][1], Ahf[mt][2], Ahf[mt][3], ah + ao);
            }
            #pragma unroll
            for (int np = 0; np < 4; np++) {
                const int brow = wc * 64 + np * 16 + ((lane >> 4) & 1) * 8 + (lane & 7);
                const int bcol = k0 + ((lane >> 3) & 1) * 8;
                const uint32_t bo = (uint32_t)(brow * LDAg + bcol) * 2;
                LDSM_X4(Bhf[2*np][0], Bhf[2*np][1], Bhf[2*np+1][0], Bhf[2*np+1][1], bh + bo);
            }

            #pragma unroll
            for (int mt = 0; mt < 2; mt++)
                #pragma unroll
                for (int nt = 0; nt < 8; nt++)
                    MMA_F16(acc[mt][nt], Ahf[mt], Bhf[nt]);
        }
    }

    const int crow = lane >> 2, ccol = (lane & 3) * 2;
    const float osc = (qscale && (bn < 1024 || bn >= 3072)) ? CSF : 1.0f;
    #pragma unroll
    for (int mt = 0; mt < 2; mt++) {
        #pragma unroll
        for (int hf2 = 0; hf2 < 2; hf2++) {
            const int r = bm + wr * 32 + mt * 16 + crow + hf2 * 8;
            #pragma unroll
            for (int nt = 0; nt < 8; nt++) {
                const int c = bn + wc * 64 + nt * 8 + ccol;
                float2 b2 = *(const float2*)&bias[c];
                float vx = (acc[mt][nt][hf2 * 2 + 0] + b2.x) * osc;
                float vy = (acc[mt][nt][hf2 * 2 + 1] + b2.y) * osc;
                if (outf) {
                    float2 v; v.x = vx; v.y = vy;
                    *(float2*)&outf[(size_t)r * N + c] = v;
                } else {
                    __half2 hh = __float22half2_rn(make_float2(vx, vy));
                    *(uint32_t*)&outh[(size_t)r * N + c] = *(uint32_t*)&hh;
                }
            }
        }
    }
}

// unified projection launch: tiles [0, T1) = QKV gemm, [T1, T1+T2) = cross gemm
#define T1_TILES 1024
#define T2_TILES 128

__global__ __launch_bounds__(256, 2) void proj_dual_kernel()
{
    extern __shared__ char smem[];
    int t = blockIdx.x;
    if (t < T1_TILES) {
        const int bn = (t & 31) * 128, bm = (t >> 5) * 128;
        gemm_body(g_xh, g_W4_h, g_b4, nullptr, g_qkvh, 4*Cc, Cc, bm, bn, 1, smem);
    } else {
        t -= T1_TILES;
        const int bn = (t & 15) * 128, bm = (t >> 4) * 128;
        gemm_body(g_ch, g_W2_h, g_b2, nullptr, g_kvch, 2*Cc, CCc, bm, bn, 0, smem);
    }
}

// ---------------------------------------------------------------------------
// Persistent fused kernel: flash attention work items, then out-proj tiles
// gated on per-row-block readiness. 2 CTAs/SM.
// ---------------------------------------------------------------------------
#define APB 144
#define QTILE (128 * APB)
#define KVTILE (64 * APB)
#define KVSTAGE (2 * KVTILE)
#define SO_OFF (QTILE + 2 * KVSTAGE)
#define ATT_SMEM (SO_OFF + 128 * 68 * 4)   // 90112 (>= SM1)
#define N_WORK (Tt / 128 * Hh * Bb)        // 512
#define N_OTILE 256                         // out-proj: 32 bm x 8 bn

__global__ __launch_bounds__(256, 2) void attn_out_kernel(
    const __half* __restrict__ qkvh, const __half* __restrict__ kvch,
    __half* __restrict__ Yh,
    const float* __restrict__ bp, float* __restrict__ out)
{
    extern __shared__ char smem[];
    const uint32_t sb = smem_u32(smem);
    float* sO = (float*)(smem + SO_OFF);
    const int tid = threadIdx.x, wid = tid >> 5, lane = tid & 31;

    const uint32_t sQh = sb;
    const uint32_t sKV = sb + QTILE;

    const int crow = lane >> 2, ccol = (lane & 3) * 2;
    const int rloc = wid * 16 + crow;

    __shared__ int s_work;

    // ======== phase A: attention work queue (heavy-qt first) ========
    for (;;) {
        if (tid == 0) s_work = atomicAdd(&g_actr, 1);
        __syncthreads();
        const int w = s_work;
        if (w >= N_WORK) break;

        const int qt = (Tt / 128 - 1) - (w >> 5);
        const int hb = w & 31;
        const int h = hb & 15, b = hb >> 4;
        const int q0 = qt * 128;
        const int wrow = q0 + wid * 16;

        for (int phase = 0; phase < 2; phase++) {
            const bool causal = (phase == 0);
            const int ldq  = 4 * Cc;
            const int ldkv = causal ? 4 * Cc : 2 * Cc;
            const int ntt  = causal ? (2 * qt + 2) : (TCc / 64);

            const __half* Qhp = causal ? qkvh        : qkvh + 3072;
            const __half* Khp = causal ? qkvh + 1024 : kvch;
            const __half* Vhp = causal ? qkvh + 2048 : kvch + 1024;

            const size_t qoff = ((size_t)b * Tt + q0) * ldq + h * Dd;
            const size_t koff = ((size_t)b * (causal ? Tt : TCc)) * ldkv + h * Dd;

            {
                const char* gq = (const char*)(Qhp + qoff);
                #pragma unroll
                for (int it = 0; it < 4; it++) {
                    int idx = it * 256 + tid;
                    int r = idx >> 3, c = idx & 7;
                    CP_ASYNC16(sQh + r * APB + c * 16,
                               gq + (size_t)r * (ldq * 2) + c * 16);
                }
            }
            CP_COMMIT();

            const char* gk[2] = { (const char*)(Khp + koff), (const char*)(Vhp + koff) };
            auto load_kv = [&](int kt, int st) {
                uint32_t dst = sKV + st * KVSTAGE;
                #pragma unroll
                for (int m = 0; m < 2; m++) {
                    #pragma unroll
                    for (int it = 0; it < 2; it++) {
                        int idx = it * 256 + tid;
                        int r = idx >> 3, c = idx & 7;
                        CP_ASYNC16(dst + m * KVTILE + r * APB + c * 16,
                                   gk[m] + ((size_t)(kt * 64 + r)) * (ldkv * 2) + c * 16);
                    }
                }
            };

            load_kv(0, 0);
            CP_COMMIT();
            CP_WAIT1();
            __syncthreads();

            uint32_t Qhf[4][4];
            {
                const int r = wid * 16 + (lane & 7) + 8 * ((lane >> 3) & 1);
                const int cb = 8 * (lane >> 4);
                #pragma unroll
                for (int kc = 0; kc < 4; kc++) {
                    const uint32_t off = (uint32_t)r * APB + (kc * 16 + cb) * 2;
                    LDSM_X4(Qhf[kc][0], Qhf[kc][1], Qhf[kc][2], Qhf[kc][3], sQh + off);
                }
            }

            float o[8][4] = {};
            float m0 = -1e30f, m1 = -1e30f, l0 = 0.f, l1 = 0.f;

            for (int kt = 0; kt < ntt; kt++) {
                const int st = kt & 1;
                if (kt + 1 < ntt) { load_kv(kt + 1, st ^ 1); CP_COMMIT(); CP_WAIT1(); }
                else              { CP_WAIT0(); }
                __syncthreads();

                const int k0 = kt * 64;
                const bool active = !causal || (k0 <= wrow + 15);
                if (active) {
                    const uint32_t sKhT = sKV + st * KVSTAGE;
                    const uint32_t sVhT = sKhT + KVTILE;

                    float s[8][4] = {};
                    {
                        const int krow = (lane & 7) + 8 * (lane >> 4);
                        const int kcolb = 8 * ((lane >> 3) & 1);
                        #pragma unroll
                        for (int kc = 0; kc < 4; kc++) {
                            uint32_t bh[8][2];
                            #pragma unroll
                            for (int np = 0; np < 4; np++) {
                                const uint32_t off =
                                    (uint32_t)(np * 16 + krow) * APB + (kc * 16 + kcolb) * 2;
                                LDSM_X4(bh[2*np][0], bh[2*np][1], bh[2*np+1][0], bh[2*np+1][1],
                                        sKhT + off);
                            }
                            #pragma unroll
                            for (int nt = 0; nt < 8; nt++)
                                MMA_F16(s[nt], Qhf[kc], bh[nt]);
                        }
                    }

                    const bool dm = causal && (k0 + 63 > wrow);
                    float zx0 = -1e30f, zx1 = -1e30f;
                    #pragma unroll
                    for (int nt = 0; nt < 8; nt++) {
                        if (dm) {
                            #pragma unroll
                            for (int r = 0; r < 4; r++) {
                                const int col = k0 + nt * 8 + ccol + (r & 1);
                                const int row = wrow + crow + 8 * (r >> 1);
                                if (col > row) s[nt][r] = -1e30f;
                            }
                        }
                        zx0 = fmaxf(zx0, fmaxf(s[nt][0], s[nt][1]));
                        zx1 = fmaxf(zx1, fmaxf(s[nt][2], s[nt][3]));
                    }
                    zx0 = fmaxf(zx0, __shfl_xor_sync(0xffffffffu, zx0, 1));
                    zx0 = fmaxf(zx0, __shfl_xor_sync(0xffffffffu, zx0, 2));
                    zx1 = fmaxf(zx1, __shfl_xor_sync(0xffffffffu, zx1, 1));
                    zx1 = fmaxf(zx1, __shfl_xor_sync(0xffffffffu, zx1, 2));
                    const float mn0 = fmaxf(m0, zx0), mn1 = fmaxf(m1, zx1);
                    const float a0 = ex2(m0 - mn0), a1 = ex2(m1 - mn1);
                    m0 = mn0; m1 = mn1;

                    float ps0 = 0.f, ps1 = 0.f;
                    uint32_t pah[4][4];
                    #pragma unroll
                    for (int nt = 0; nt < 8; nt++) {
                        const float p0 = ex2(s[nt][0] - mn0), p1 = ex2(s[nt][1] - mn0);
                        const float p2 = ex2(s[nt][2] - mn1), p3 = ex2(s[nt][3] - mn1);
                        ps0 += p0 + p1; ps1 += p2 + p3;
                        __half2 h01 = __float22half2_rn(make_float2(p0, p1));
                        __half2 h23 = __float22half2_rn(make_float2(p2, p3));
                        pah[nt >> 1][(nt & 1) * 2 + 0] = *(uint32_t*)&h01;
                        pah[nt >> 1][(nt & 1) * 2 + 1] = *(uint32_t*)&h23;
                    }
                    l0 = l0 * a0 + ps0;
                    l1 = l1 * a1 + ps1;
                    #pragma unroll
                    for (int nt = 0; nt < 8; nt++) {
                        o[nt][0] *= a0; o[nt][1] *= a0;
                        o[nt][2] *= a1; o[nt][3] *= a1;
                    }

                    {
                        const int vrl = (lane & 7) + 8 * ((lane >> 3) & 1);
                        const int vcb = 8 * (lane >> 4);
                        #pragma unroll
                        for (int kc = 0; kc < 4; kc++) {
                            uint32_t vh[8][2];
                            #pragma unroll
                            for (int dp = 0; dp < 4; dp++) {
                                const uint32_t off =
                                    (uint32_t)(kc * 16 + vrl) * APB + (dp * 16 + vcb) * 2;
                                LDSM_X4T(vh[2*dp][0], vh[2*dp][1], vh[2*dp+1][0], vh[2*dp+1][1],
                                         sVhT + off);
                            }
                            #pragma unroll
                            for (int nt = 0; nt < 8; nt++)
                                MMA_F16(o[nt], pah[kc], vh[nt]);
                        }
                    }
                }
                __syncthreads();
            }

            l0 += __shfl_xor_sync(0xffffffffu, l0, 1);
            l0 += __shfl_xor_sync(0xffffffffu, l0, 2);
            l1 += __shfl_xor_sync(0xffffffffu, l1, 1);
            l1 += __shfl_xor_sync(0xffffffffu, l1, 2);
            const float i0 = 1.f / l0, i1 = 1.f / l1;

            if (phase == 0) {
                #pragma unroll
                for (int nt = 0; nt < 8; nt++) {
                    const int c = nt * 8 + ccol;
                    sO[rloc * 68 + c]           = o[nt][0] * i0;
                    sO[rloc * 68 + c + 1]       = o[nt][1] * i0;
                    sO[(rloc + 8) * 68 + c]     = o[nt][2] * i1;
                    sO[(rloc + 8) * 68 + c + 1] = o[nt][3] * i1;
                }
            } else {
                const int r0 = q0 + wid * 16 + crow;
                __half* yh0 = Yh + ((size_t)b * Tt + r0) * Cc + h * Dd;
                __half* yh1 = yh0 + 8 * Cc;
                #pragma unroll
                for (int nt = 0; nt < 8; nt++) {
                    const int c = nt * 8 + ccol;
                    float vx0 = sO[rloc * 68 + c]           + o[nt][0] * i0;
                    float vy0 = sO[rloc * 68 + c + 1]       + o[nt][1] * i0;
                    float vx1 = sO[(rloc + 8) * 68 + c]     + o[nt][2] * i1;
                    float vy1 = sO[(rloc + 8) * 68 + c + 1] + o[nt][3] * i1;
                    __half2 h0 = __float22half2_rn(make_float2(vx0, vy0));
                    __half2 h1 = __float22half2_rn(make_float2(vx1, vy1));
                    *(uint32_t*)&yh0[c] = *(uint32_t*)&h0;
                    *(uint32_t*)&yh1[c] = *(uint32_t*)&h1;
                }
            }
        }

        // signal row-block completion (all 256 threads' y stores fenced)
        __threadfence();
        __syncthreads();
        if (tid == 0) atomicAdd(&g_rowcnt[b * 16 + qt], 1);
        __syncthreads();
    }

    // ======== phase B: out projection tiles, gated on row readiness ========
    // tile order matches attention completion: rb = {15,31}, {14,30}, ...
    for (;;) {
        if (tid == 0) s_work = atomicAdd(&g_octr, 1);
        __syncthreads();
        const int t = s_work;
        if (t >= N_OTILE) break;

        const int g = t >> 4, u = t & 15;
        const int rb = (u & 1) ? (31 - g) : (15 - g);
        const int bn = (u >> 1) * 128;
        const int bm = rb * 128;

        if (tid == 0) {
            volatile int* rc = (volatile int*)&g_rowcnt[rb];
            while (*rc < 16) { }
        }
        __syncthreads();
        __threadfence();   // acquire: make producers' y stores visible

        gemm_body(g_yh, g_Wp_h, bp, out, nullptr, Cc, Cc, bm, bn, 0, smem);
        __syncthreads();
    }
}

// ---------------------------------------------------------------------------

extern "C" void kernel_launch(void* const* d_in, const int* in_sizes, int n_in,
                              void* d_out, int out_size)
{
    const float* x     = (const float*)d_in[0];
    const float* cross = (const float*)d_in[1];
    const float* Wk  = (const float*)d_in[2];   const float* bk  = (const float*)d_in[3];
    const float* Wq  = (const float*)d_in[4];   const float* bq  = (const float*)d_in[5];
    const float* Wv  = (const float*)d_in[6];   const float* bv  = (const float*)d_in[7];
    const float* Wck = (const float*)d_in[8];   const float* bck = (const float*)d_in[9];
    const float* Wcq = (const float*)d_in[10];  const float* bcq = (const float*)d_in[11];
    const float* Wcv = (const float*)d_in[12];  const float* bcv = (const float*)d_in[13];
    const float* Wp  = (const float*)d_in[14];  const float* bp  = (const float*)d_in[15];
    float* out = (float*)d_out;

    __half *qkvh, *kvch, *yh;
    cudaGetSymbolAddress((void**)&qkvh, g_qkvh);
    cudaGetSymbolAddress((void**)&kvch, g_kvch);
    cudaGetSymbolAddress((void**)&yh, g_yh);

    // merged prep: transposes + cvt + bias + counter resets, one launch
    const int misc_blocks = (MISC_N + 255) / 256;
    prep_kernel<<<TRB + misc_blocks, 256>>>(
        x, cross, Wq, Wk, Wv, Wcq, Wck, Wcv, Wp, bq, bk, bv, bcq, bck, bcv);

    cudaFuncSetAttribute(proj_dual_kernel, cudaFuncAttributeMaxDynamicSharedMemorySize, SM1);
    cudaFuncSetAttribute(attn_out_kernel, cudaFuncAttributeMaxDynamicSharedMemorySize, ATT_SMEM);
    const dim3 gblk(256);

    // unified projections
    proj_dual_kernel<<<T1_TILES + T2_TILES, gblk, SM1>>>();

    // persistent attention + overlapped out-projection
    attn_out_kernel<<<296, gblk, ATT_SMEM>>>(qkvh, kvch, yh, bp, out);
}

// round 17
// speedup vs baseline: 1.0295x; 1.0295x over previous
#include <cuda_runtime.h>
#include <cuda_fp16.h>
#include <cstdint>
#include <math.h>

#define Bb 2
#define Tt 2048
#define TCc 512
#define Cc 1024
#define CCc 512
#define Hh 16
#define Dd 64

#define NX (Bb*Tt*Cc)      // 4194304
#define NC (Bb*TCc*CCc)    // 524288

// ---------------------------------------------------------------------------
// Scratch (__device__ globals; no allocation allowed)
// ---------------------------------------------------------------------------
__device__ __half g_xh[NX];
__device__ __half g_ch[NC];
__device__ __half g_yh[Bb*Tt*Cc];

// fused projection outputs: [B*T, 4096] = [q | k | v | qc], single fp16
// q and qc columns are PRE-SCALED by cs = 0.125 * log2(e).
__device__ __half g_qkvh[Bb*Tt*4*Cc];
// fused cross outputs: [B*TC, 2048] = [kc | vc], single fp16
__device__ __half g_kvch[Bb*TCc*2*Cc];

// fused transposed weights (single fp16)
__device__ __half g_W4_h[4*Cc*Cc];
__device__ __half g_W2_h[2*Cc*CCc];
__device__ __half g_Wp_h[Cc*Cc];
__device__ float g_b4[4*Cc], g_b2[2*Cc];

// persistent work counters + row-block readiness
__device__ int g_actr;          // attention work items
__device__ int g_octr;          // out-proj tiles
__device__ int g_rowcnt[32];    // heads completed per 128-row block of y

#define CSF 0.18033688011f   // 0.125 * log2(e)

// ---------------------------------------------------------------------------
// helpers
// ---------------------------------------------------------------------------
__device__ __forceinline__ uint32_t smem_u32(const void* p) {
    uint32_t a;
    asm("{ .reg .u64 t; cvta.to.shared.u64 t, %1; cvt.u32.u64 %0, t; }"
        : "=r"(a) : "l"(p));
    return a;
}
__device__ __forceinline__ float ex2(float x) {
    float y; asm("ex2.approx.ftz.f32 %0, %1;" : "=f"(y) : "f"(x)); return y;
}

#define CP_ASYNC16(dst, src) \
    asm volatile("cp.async.cg.shared.global [%0], [%1], 16;" :: "r"(dst), "l"(src))
#define CP_COMMIT() asm volatile("cp.async.commit_group;" ::: "memory")
#define CP_WAIT0()  asm volatile("cp.async.wait_group 0;" ::: "memory")
#define CP_WAIT1()  asm volatile("cp.async.wait_group 1;" ::: "memory")

#define LDSM_X4(r0, r1, r2, r3, a) \
    asm volatile("ldmatrix.sync.aligned.m8n8.x4.shared.b16 {%0,%1,%2,%3}, [%4];" \
                 : "=r"(r0), "=r"(r1), "=r"(r2), "=r"(r3) : "r"(a))
#define LDSM_X4T(r0, r1, r2, r3, a) \
    asm volatile("ldmatrix.sync.aligned.m8n8.x4.trans.shared.b16 {%0,%1,%2,%3}, [%4];" \
                 : "=r"(r0), "=r"(r1), "=r"(r2), "=r"(r3) : "r"(a))

#define MMA_F16(d, a, b) \
    asm volatile("mma.sync.aligned.m16n8k16.row.col.f32.f16.f16.f32 " \
                 "{%0,%1,%2,%3}, {%4,%5,%6,%7}, {%8,%9}, {%0,%1,%2,%3};" \
                 : "+f"((d)[0]), "+f"((d)[1]), "+f"((d)[2]), "+f"((d)[3]) \
                 : "r"((a)[0]), "r"((a)[1]), "r"((a)[2]), "r"((a)[3]), \
                   "r"((b)[0]), "r"((b)[1]))

// ---------------------------------------------------------------------------
// merged prep kernel (bandwidth-optimized):
//   blocks [0, TRB): weight transposes, 64k x 32n tiles,
//                    128B coalesced reads AND writes per warp
//   blocks [TRB, ..): vectorized cvt x / cross (float4 -> 2x half2),
//                     bias concat, counter resets
// ---------------------------------------------------------------------------
#define TRB 3072
#define X4 (NX / 4)            // 1048576
#define C4 (NC / 4)            // 131072
#define MISC_N (X4 + C4 + 6144 + 40)

__global__ void prep_kernel(
    const float* __restrict__ x, const float* __restrict__ cross,
    const float* __restrict__ Wq,  const float* __restrict__ Wk,
    const float* __restrict__ Wv,  const float* __restrict__ Wcq,
    const float* __restrict__ Wck, const float* __restrict__ Wcv,
    const float* __restrict__ Wp,
    const float* __restrict__ bq, const float* __restrict__ bk,
    const float* __restrict__ bv, const float* __restrict__ bcq,
    const float* __restrict__ bck, const float* __restrict__ bcv)
{
    const int blk = blockIdx.x;
    const int tid = threadIdx.x;

    if (blk < TRB) {
        // ---- weight transpose: one 64k x 32n tile ----
        int z, base;
        if (blk < 2048)      { z = blk >> 9;  base = blk & 511; }
        else if (blk < 2304) { z = 4;         base = blk - 2048; }
        else if (blk < 2560) { z = 5;         base = blk - 2304; }
        else                 { z = 6;         base = blk - 2560; }
        const float* W;
        __half* Th;
        int K;
        switch (z) {
            case 0: W = Wq;  Th = g_W4_h;               K = 1024; break;
            case 1: W = Wk;  Th = g_W4_h + 1024 * 1024; K = 1024; break;
            case 2: W = Wv;  Th = g_W4_h + 2048 * 1024; K = 1024; break;
            case 3: W = Wcq; Th = g_W4_h + 3072 * 1024; K = 1024; break;
            case 4: W = Wck; Th = g_W2_h;               K = 512;  break;
            case 5: W = Wcv; Th = g_W2_h + 1024 * 512;  K = 512;  break;
            default: W = Wp; Th = g_Wp_h;               K = 1024; break;
        }
        const int k0 = (base >> 5) * 64;
        const int n0 = (base & 31) * 32;

        __shared__ float t[64][33];
        // load 64 k-rows x 32 n-cols, coalesced (n contiguous)
        #pragma unroll
        for (int it = 0; it < 8; it++) {
            const int idx = it * 256 + tid;
            const int r = idx >> 5, c = idx & 31;
            t[r][c] = W[(size_t)(k0 + r) * 1024 + n0 + c];
        }
        __syncthreads();
        // write 32 n-rows x 32 k-pairs as half2, 128B contiguous per warp
        #pragma unroll
        for (int it = 0; it < 4; it++) {
            const int idx = it * 256 + tid;
            const int n = idx >> 5, jp = idx & 31;
            __half2 v = __floats2half2_rn(t[2 * jp][n], t[2 * jp + 1][n]);
            *(__half2*)&Th[(size_t)(n0 + n) * K + k0 + 2 * jp] = v;
        }
        return;
    }

    // ---- misc: vectorized cvt + bias concat + counters ----
    const int i = (blk - TRB) * 256 + tid;
    if (i < X4) {
        float4 v = ((const float4*)x)[i];
        __half2 h0 = __floats2half2_rn(v.x, v.y);
        __half2 h1 = __floats2half2_rn(v.z, v.w);
        uint2 u = { *(uint32_t*)&h0, *(uint32_t*)&h1 };
        ((uint2*)g_xh)[i] = u;
    } else if (i < X4 + C4) {
        float4 v = ((const float4*)cross)[i - X4];
        __half2 h0 = __floats2half2_rn(v.x, v.y);
        __half2 h1 = __floats2half2_rn(v.z, v.w);
        uint2 u = { *(uint32_t*)&h0, *(uint32_t*)&h1 };
        ((uint2*)g_ch)[i - X4] = u;
    } else if (i < X4 + C4 + 6144) {
        int j = i - X4 - C4;
        if (j < 4096) {
            const float* s[4] = {bq, bk, bv, bcq};
            g_b4[j] = s[j >> 10][j & 1023];
        } else {
            int k = j - 4096;
            g_b2[k] = (k < 1024) ? bck[k] : bcv[k - 1024];
        }
    } else if (i < MISC_N) {
        int j = i - (X4 + C4 + 6144);
        if (j == 0) g_actr = 0;
        else if (j == 1) g_octr = 0;
        else if (j < 34) g_rowcnt[j - 2] = 0;
    }
}

// ---------------------------------------------------------------------------
// single-term HMMA GEMM body
// ---------------------------------------------------------------------------
#define BKg 32
#define LDAg 40
#define TILEB (128 * LDAg * 2)
#define STG1 (2 * TILEB)
#define SM1 (3 * STG1)          // 61440

__device__ __forceinline__ void gemm_body(
    const __half* Ah, const __half* Bh, const float* bias,
    float* outf, __half* outh,
    int N, int K, int bm, int bn, int qscale, char* smem)
{
    const uint32_t sb = smem_u32(smem);
    const int tid = threadIdx.x;
    const int wid = tid >> 5, lane = tid & 31;
    const int wr = wid & 3;
    const int wc = wid >> 2;

    const char* gA = (const char*)(Ah + (size_t)bm * K);
    const char* gB = (const char*)(Bh + (size_t)bn * K);

    const int row0 = tid >> 2, c16a = tid & 3;
    const int row1 = (tid + 256) >> 2;

    auto load_tile = [&](const char* g, uint32_t d, int kb) {
        g += (size_t)kb * (BKg * 2);
        CP_ASYNC16(d + row0 * (LDAg * 2) + c16a * 16,
                   g + (size_t)row0 * (K * 2) + c16a * 16);
        CP_ASYNC16(d + row1 * (LDAg * 2) + c16a * 16,
                   g + (size_t)row1 * (K * 2) + c16a * 16);
    };
    auto load_chunk = [&](int kb, int st) {
        const uint32_t sdst = sb + st * STG1;
        load_tile(gA, sdst, kb);
        load_tile(gB, sdst + TILEB, kb);
    };

    float acc[2][8][4] = {};

    const int nchunks = K / BKg;
    load_chunk(0, 0); CP_COMMIT();
    load_chunk(1, 1); CP_COMMIT();

    for (int kb = 0; kb < nchunks; kb++) {
        const int st = kb % 3;
        if (kb + 1 < nchunks) { CP_WAIT1(); } else { CP_WAIT0(); }
        __syncthreads();
        if (kb + 2 < nchunks) { load_chunk(kb + 2, (kb + 2) % 3); CP_COMMIT(); }

        const uint32_t ah = sb + st * STG1;
        const uint32_t bh = ah + TILEB;

        #pragma unroll
        for (int ks = 0; ks < 2; ks++) {
            const int k0 = ks * 16;
            uint32_t Ahf[2][4], Bhf[8][2];

            #pragma unroll
            for (int mt = 0; mt < 2; mt++) {
                const int arow = wr * 32 + mt * 16 + (lane & 15);
                const int acol = k0 + (lane >> 4) * 8;
                const uint32_t ao = (uint32_t)(arow * LDAg + acol) * 2;
                LDSM_X4(Ahf[mt][0], Ahf[mt][1], Ahf[mt][2], Ahf[mt][3], ah + ao);
            }
            #pragma unroll
            for (int np = 0; np < 4; np++) {
                const int brow = wc * 64 + np * 16 + ((lane >> 4) & 1) * 8 + (lane & 7);
                const int bcol = k0 + ((lane >> 3) & 1) * 8;
                const uint32_t bo = (uint32_t)(brow * LDAg + bcol) * 2;
                LDSM_X4(Bhf[2*np][0], Bhf[2*np][1], Bhf[2*np+1][0], Bhf[2*np+1][1], bh + bo);
            }

            #pragma unroll
            for (int mt = 0; mt < 2; mt++)
                #pragma unroll
                for (int nt = 0; nt < 8; nt++)
                    MMA_F16(acc[mt][nt], Ahf[mt], Bhf[nt]);
        }
    }

    const int crow = lane >> 2, ccol = (lane & 3) * 2;
    const float osc = (qscale && (bn < 1024 || bn >= 3072)) ? CSF : 1.0f;
    #pragma unroll
    for (int mt = 0; mt < 2; mt++) {
        #pragma unroll
        for (int hf2 = 0; hf2 < 2; hf2++) {
            const int r = bm + wr * 32 + mt * 16 + crow + hf2 * 8;
            #pragma unroll
            for (int nt = 0; nt < 8; nt++) {
                const int c = bn + wc * 64 + nt * 8 + ccol;
                float2 b2 = *(const float2*)&bias[c];
                float vx = (acc[mt][nt][hf2 * 2 + 0] + b2.x) * osc;
                float vy = (acc[mt][nt][hf2 * 2 + 1] + b2.y) * osc;
                if (outf) {
                    float2 v; v.x = vx; v.y = vy;
                    *(float2*)&outf[(size_t)r * N + c] = v;
                } else {
                    __half2 hh = __float22half2_rn(make_float2(vx, vy));
                    *(uint32_t*)&outh[(size_t)r * N + c] = *(uint32_t*)&hh;
                }
            }
        }
    }
}

// unified projection launch: tiles [0, T1) = QKV gemm, [T1, T1+T2) = cross gemm
#define T1_TILES 1024
#define T2_TILES 128

__global__ __launch_bounds__(256, 2) void proj_dual_kernel()
{
    extern __shared__ char smem[];
    int t = blockIdx.x;
    if (t < T1_TILES) {
        const int bn = (t & 31) * 128, bm = (t >> 5) * 128;
        gemm_body(g_xh, g_W4_h, g_b4, nullptr, g_qkvh, 4*Cc, Cc, bm, bn, 1, smem);
    } else {
        t -= T1_TILES;
        const int bn = (t & 15) * 128, bm = (t >> 4) * 128;
        gemm_body(g_ch, g_W2_h, g_b2, nullptr, g_kvch, 2*Cc, CCc, bm, bn, 0, smem);
    }
}

// ---------------------------------------------------------------------------
// Persistent fused kernel: flash attention work items, then out-proj tiles
// gated on per-row-block readiness. 2 CTAs/SM.
// ---------------------------------------------------------------------------
#define APB 144
#define QTILE (128 * APB)
#define KVTILE (64 * APB)
#define KVSTAGE (2 * KVTILE)
#define SO_OFF (QTILE + 2 * KVSTAGE)
#define ATT_SMEM (SO_OFF + 128 * 68 * 4)   // 90112 (>= SM1)
#define N_WORK (Tt / 128 * Hh * Bb)        // 512
#define N_OTILE 256                         // out-proj: 32 bm x 8 bn

__global__ __launch_bounds__(256, 2) void attn_out_kernel(
    const __half* __restrict__ qkvh, const __half* __restrict__ kvch,
    __half* __restrict__ Yh,
    const float* __restrict__ bp, float* __restrict__ out)
{
    extern __shared__ char smem[];
    const uint32_t sb = smem_u32(smem);
    float* sO = (float*)(smem + SO_OFF);
    const int tid = threadIdx.x, wid = tid >> 5, lane = tid & 31;

    const uint32_t sQh = sb;
    const uint32_t sKV = sb + QTILE;

    const int crow = lane >> 2, ccol = (lane & 3) * 2;
    const int rloc = wid * 16 + crow;

    __shared__ int s_work;

    // ======== phase A: attention work queue (heavy-qt first) ========
    for (;;) {
        if (tid == 0) s_work = atomicAdd(&g_actr, 1);
        __syncthreads();
        const int w = s_work;
        if (w >= N_WORK) break;

        const int qt = (Tt / 128 - 1) - (w >> 5);
        const int hb = w & 31;
        const int h = hb & 15, b = hb >> 4;
        const int q0 = qt * 128;
        const int wrow = q0 + wid * 16;

        for (int phase = 0; phase < 2; phase++) {
            const bool causal = (phase == 0);
            const int ldq  = 4 * Cc;
            const int ldkv = causal ? 4 * Cc : 2 * Cc;
            const int ntt  = causal ? (2 * qt + 2) : (TCc / 64);

            const __half* Qhp = causal ? qkvh        : qkvh + 3072;
            const __half* Khp = causal ? qkvh + 1024 : kvch;
            const __half* Vhp = causal ? qkvh + 2048 : kvch + 1024;

            const size_t qoff = ((size_t)b * Tt + q0) * ldq + h * Dd;
            const size_t koff = ((size_t)b * (causal ? Tt : TCc)) * ldkv + h * Dd;

            {
                const char* gq = (const char*)(Qhp + qoff);
                #pragma unroll
                for (int it = 0; it < 4; it++) {
                    int idx = it * 256 + tid;
                    int r = idx >> 3, c = idx & 7;
                    CP_ASYNC16(sQh + r * APB + c * 16,
                               gq + (size_t)r * (ldq * 2) + c * 16);
                }
            }
            CP_COMMIT();

            const char* gk[2] = { (const char*)(Khp + koff), (const char*)(Vhp + koff) };
            auto load_kv = [&](int kt, int st) {
                uint32_t dst = sKV + st * KVSTAGE;
                #pragma unroll
                for (int m = 0; m < 2; m++) {
                    #pragma unroll
                    for (int it = 0; it < 2; it++) {
                        int idx = it * 256 + tid;
                        int r = idx >> 3, c = idx & 7;
                        CP_ASYNC16(dst + m * KVTILE + r * APB + c * 16,
                                   gk[m] + ((size_t)(kt * 64 + r)) * (ldkv * 2) + c * 16);
                    }
                }
            };

            load_kv(0, 0);
            CP_COMMIT();
            CP_WAIT1();
            __syncthreads();

            uint32_t Qhf[4][4];
            {
                const int r = wid * 16 + (lane & 7) + 8 * ((lane >> 3) & 1);
                const int cb = 8 * (lane >> 4);
                #pragma unroll
                for (int kc = 0; kc < 4; kc++) {
                    const uint32_t off = (uint32_t)r * APB + (kc * 16 + cb) * 2;
                    LDSM_X4(Qhf[kc][0], Qhf[kc][1], Qhf[kc][2], Qhf[kc][3], sQh + off);
                }
            }

            float o[8][4] = {};
            float m0 = -1e30f, m1 = -1e30f, l0 = 0.f, l1 = 0.f;

            for (int kt = 0; kt < ntt; kt++) {
                const int st = kt & 1;
                if (kt + 1 < ntt) { load_kv(kt + 1, st ^ 1); CP_COMMIT(); CP_WAIT1(); }
                else              { CP_WAIT0(); }
                __syncthreads();

                const int k0 = kt * 64;
                const bool active = !causal || (k0 <= wrow + 15);
                if (active) {
                    const uint32_t sKhT = sKV + st * KVSTAGE;
                    const uint32_t sVhT = sKhT + KVTILE;

                    float s[8][4] = {};
                    {
                        const int krow = (lane & 7) + 8 * (lane >> 4);
                        const int kcolb = 8 * ((lane >> 3) & 1);
                        #pragma unroll
                        for (int kc = 0; kc < 4; kc++) {
                            uint32_t bh[8][2];
                            #pragma unroll
                            for (int np = 0; np < 4; np++) {
                                const uint32_t off =
                                    (uint32_t)(np * 16 + krow) * APB + (kc * 16 + kcolb) * 2;
                                LDSM_X4(bh[2*np][0], bh[2*np][1], bh[2*np+1][0], bh[2*np+1][1],
                                        sKhT + off);
                            }
                            #pragma unroll
                            for (int nt = 0; nt < 8; nt++)
                                MMA_F16(s[nt], Qhf[kc], bh[nt]);
                        }
                    }

                    const bool dm = causal && (k0 + 63 > wrow);
                    float zx0 = -1e30f, zx1 = -1e30f;
                    #pragma unroll
                    for (int nt = 0; nt < 8; nt++) {
                        if (dm) {
                            #pragma unroll
                            for (int r = 0; r < 4; r++) {
                                const int col = k0 + nt * 8 + ccol + (r & 1);
                                const int row = wrow + crow + 8 * (r >> 1);
                                if (col > row) s[nt][r] = -1e30f;
                            }
                        }
                        zx0 = fmaxf(zx0, fmaxf(s[nt][0], s[nt][1]));
                        zx1 = fmaxf(zx1, fmaxf(s[nt][2], s[nt][3]));
                    }
                    zx0 = fmaxf(zx0, __shfl_xor_sync(0xffffffffu, zx0, 1));
                    zx0 = fmaxf(zx0, __shfl_xor_sync(0xffffffffu, zx0, 2));
                    zx1 = fmaxf(zx1, __shfl_xor_sync(0xffffffffu, zx1, 1));
                    zx1 = fmaxf(zx1, __shfl_xor_sync(0xffffffffu, zx1, 2));
                    const float mn0 = fmaxf(m0, zx0), mn1 = fmaxf(m1, zx1);
                    const float a0 = ex2(m0 - mn0), a1 = ex2(m1 - mn1);
                    m0 = mn0; m1 = mn1;

                    float ps0 = 0.f, ps1 = 0.f;
                    uint32_t pah[4][4];
                    #pragma unroll
                    for (int nt = 0; nt < 8; nt++) {
                        const float p0 = ex2(s[nt][0] - mn0), p1 = ex2(s[nt][1] - mn0);
                        const float p2 = ex2(s[nt][2] - mn1), p3 = ex2(s[nt][3] - mn1);
                        ps0 += p0 + p1; ps1 += p2 + p3;
                        __half2 h01 = __float22half2_rn(make_float2(p0, p1));
                        __half2 h23 = __float22half2_rn(make_float2(p2, p3));
                        pah[nt >> 1][(nt & 1) * 2 + 0] = *(uint32_t*)&h01;
                        pah[nt >> 1][(nt & 1) * 2 + 1] = *(uint32_t*)&h23;
                    }
                    l0 = l0 * a0 + ps0;
                    l1 = l1 * a1 + ps1;
                    #pragma unroll
                    for (int nt = 0; nt < 8; nt++) {
                        o[nt][0] *= a0; o[nt][1] *= a0;
                        o[nt][2] *= a1; o[nt][3] *= a1;
                    }

                    {
                        const int vrl = (lane & 7) + 8 * ((lane >> 3) & 1);
                        const int vcb = 8 * (lane >> 4);
                        #pragma unroll
                        for (int kc = 0; kc < 4; kc++) {
                            uint32_t vh[8][2];
                            #pragma unroll
                            for (int dp = 0; dp < 4; dp++) {
                                const uint32_t off =
                                    (uint32_t)(kc * 16 + vrl) * APB + (dp * 16 + vcb) * 2;
                                LDSM_X4T(vh[2*dp][0], vh[2*dp][1], vh[2*dp+1][0], vh[2*dp+1][1],
                                         sVhT + off);
                            }
                            #pragma unroll
                            for (int nt = 0; nt < 8; nt++)
                                MMA_F16(o[nt], pah[kc], vh[nt]);
                        }
                    }
                }
                __syncthreads();
            }

            l0 += __shfl_xor_sync(0xffffffffu, l0, 1);
            l0 += __shfl_xor_sync(0xffffffffu, l0, 2);
            l1 += __shfl_xor_sync(0xffffffffu, l1, 1);
            l1 += __shfl_xor_sync(0xffffffffu, l1, 2);
            const float i0 = 1.f / l0, i1 = 1.f / l1;

            if (phase == 0) {
                #pragma unroll
                for (int nt = 0; nt < 8; nt++) {
                    const int c = nt * 8 + ccol;
                    sO[rloc * 68 + c]           = o[nt][0] * i0;
                    sO[rloc * 68 + c + 1]       = o[nt][1] * i0;
                    sO[(rloc + 8) * 68 + c]     = o[nt][2] * i1;
                    sO[(rloc + 8) * 68 + c + 1] = o[nt][3] * i1;
                }
            } else {
                const int r0 = q0 + wid * 16 + crow;
                __half* yh0 = Yh + ((size_t)b * Tt + r0) * Cc + h * Dd;
                __half* yh1 = yh0 + 8 * Cc;
                #pragma unroll
                for (int nt = 0; nt < 8; nt++) {
                    const int c = nt * 8 + ccol;
                    float vx0 = sO[rloc * 68 + c]           + o[nt][0] * i0;
                    float vy0 = sO[rloc * 68 + c + 1]       + o[nt][1] * i0;
                    float vx1 = sO[(rloc + 8) * 68 + c]     + o[nt][2] * i1;
                    float vy1 = sO[(rloc + 8) * 68 + c + 1] + o[nt][3] * i1;
                    __half2 h0 = __float22half2_rn(make_float2(vx0, vy0));
                    __half2 h1 = __float22half2_rn(make_float2(vx1, vy1));
                    *(uint32_t*)&yh0[c] = *(uint32_t*)&h0;
                    *(uint32_t*)&yh1[c] = *(uint32_t*)&h1;
                }
            }
        }

        // signal row-block completion
        __threadfence();
        __syncthreads();
        if (tid == 0) atomicAdd(&g_rowcnt[b * 16 + qt], 1);
        __syncthreads();
    }

    // ======== phase B: out projection tiles, gated on row readiness ========
    for (;;) {
        if (tid == 0) s_work = atomicAdd(&g_octr, 1);
        __syncthreads();
        const int t = s_work;
        if (t >= N_OTILE) break;

        const int g = t >> 4, u = t & 15;
        const int rb = (u & 1) ? (31 - g) : (15 - g);
        const int bn = (u >> 1) * 128;
        const int bm = rb * 128;

        if (tid == 0) {
            volatile int* rc = (volatile int*)&g_rowcnt[rb];
            while (*rc < 16) { }
        }
        __syncthreads();
        __threadfence();

        gemm_body(g_yh, g_Wp_h, bp, out, nullptr, Cc, Cc, bm, bn, 0, smem);
        __syncthreads();
    }
}

// ---------------------------------------------------------------------------

extern "C" void kernel_launch(void* const* d_in, const int* in_sizes, int n_in,
                              void* d_out, int out_size)
{
    const float* x     = (const float*)d_in[0];
    const float* cross = (const float*)d_in[1];
    const float* Wk  = (const float*)d_in[2];   const float* bk  = (const float*)d_in[3];
    const float* Wq  = (const float*)d_in[4];   const float* bq  = (const float*)d_in[5];
    const float* Wv  = (const float*)d_in[6];   const float* bv  = (const float*)d_in[7];
    const float* Wck = (const float*)d_in[8];   const float* bck = (const float*)d_in[9];
    const float* Wcq = (const float*)d_in[10];  const float* bcq = (const float*)d_in[11];
    const float* Wcv = (const float*)d_in[12];  const float* bcv = (const float*)d_in[13];
    const float* Wp  = (const float*)d_in[14];  const float* bp  = (const float*)d_in[15];
    float* out = (float*)d_out;

    __half *qkvh, *kvch, *yh;
    cudaGetSymbolAddress((void**)&qkvh, g_qkvh);
    cudaGetSymbolAddress((void**)&kvch, g_kvch);
    cudaGetSymbolAddress((void**)&yh, g_yh);

    // merged prep: transposes + vectorized cvt + bias + counter resets
    const int misc_blocks = (MISC_N + 255) / 256;
    prep_kernel<<<TRB + misc_blocks, 256>>>(
        x, cross, Wq, Wk, Wv, Wcq, Wck, Wcv, Wp, bq, bk, bv, bcq, bck, bcv);

    cudaFuncSetAttribute(proj_dual_kernel, cudaFuncAttributeMaxDynamicSharedMemorySize, SM1);
    cudaFuncSetAttribute(attn_out_kernel, cudaFuncAttributeMaxDynamicSharedMemorySize, ATT_SMEM);
    const dim3 gblk(256);

    // unified projections
    proj_dual_kernel<<<T1_TILES + T2_TILES, gblk, SM1>>>();

    // persistent attention + overlapped out-projection
    attn_out_kernel<<<296, gblk, ATT_SMEM>>>(qkvh, kvch, yh, bp, out);
}